// round 10
// baseline (speedup 1.0000x reference)
#include <cuda_runtime.h>
#include <cuda_bf16.h>
#include <math.h>
#include <stdint.h>

// ---------------- problem constants ----------------
#define NN     200000
#define NEDGE  800000
#define CBB    480
#define CT     484
#define FDIM   128
#define NPIX   (FDIM*FDIM)
#define HID    128
#define KIN    488

// ---------------- smem layout (bytes) ----------------
#define TILE1    10240                  // 128 rows x 40 bf16 (80B stride)
#define A1_OFF(b)   ((b)*2*TILE1)       // hi at +0, lo at +TILE1
#define B1_OFF(b)   (40960 + (b)*2*TILE1)
#define A2_STR   272                    // h1 tile row stride bytes
#define A2H_OFF  0                      // overlaps GEMM1 A/B region (after GEMM1)
#define A2L_OFF  34816
#define A2_LODELTA (A2L_OFF - A2H_OFF)
#define B2_OFF   81920                  // hi +0, lo +TILE1
#define PQ_OFF   102400                 // int4[128]
#define WQ_OFF   104448                 // float4[128]
#define SQ_OFF   106496                 // float4[128]
#define SMEM_BYTES 108544

// ---------------- device scratch ----------------
__device__ float g_ft[(size_t)NPIX * CT];     // (pixel, channel) fp32 feature map
__device__ __nv_bfloat16 g_W1h[128*512];      // [n][k'=512] hi
__device__ __nv_bfloat16 g_W1l[128*512];      // lo
__device__ __nv_bfloat16 g_W2h[128*128];      // [n][k=128] hi
__device__ __nv_bfloat16 g_W2l[128*128];
__device__ int g_deg[NN];
__device__ int g_maxdeg;
__device__ int g_e64;

// ---------------- helpers ----------------
__device__ __forceinline__ void cp16(void* s, const void* g) {
    unsigned ss = (unsigned)__cvta_generic_to_shared(s);
    asm volatile("cp.async.cg.shared.global [%0], [%1], 16;" :: "r"(ss), "l"(g));
}
#define CP_COMMIT() asm volatile("cp.async.commit_group;")
#define CP_WAIT0()  asm volatile("cp.async.wait_group 0;" ::: "memory")

__device__ __forceinline__ uint32_t sm32(const void* p) {
    return (uint32_t)__cvta_generic_to_shared(p);
}
__device__ __forceinline__ void ldsm4(uint32_t* r, uint32_t a) {
    asm volatile("ldmatrix.sync.aligned.m8n8.x4.shared.b16 {%0,%1,%2,%3}, [%4];"
        : "=r"(r[0]), "=r"(r[1]), "=r"(r[2]), "=r"(r[3]) : "r"(a));
}
__device__ __forceinline__ void mma16816(float* d, const uint32_t* a, uint32_t b0, uint32_t b1) {
    asm("mma.sync.aligned.m16n8k16.row.col.f32.bf16.bf16.f32 "
        "{%0,%1,%2,%3}, {%4,%5,%6,%7}, {%8,%9}, {%0,%1,%2,%3};"
        : "+f"(d[0]), "+f"(d[1]), "+f"(d[2]), "+f"(d[3])
        : "r"(a[0]), "r"(a[1]), "r"(a[2]), "r"(a[3]), "r"(b0), "r"(b1));
}

__device__ __forceinline__ void bld_issue(const int4* __restrict__ Pq, int m, int k, float2* f) {
    if (k < CT) {
        int4 q = Pq[m];
        const float* __restrict__ ft = g_ft;
        f[0] = *(const float2*)(ft + q.x + k);
        f[1] = *(const float2*)(ft + q.y + k);
        f[2] = *(const float2*)(ft + q.z + k);
        f[3] = *(const float2*)(ft + q.w + k);
    }
}

__device__ __forceinline__ void bld_store(const float4* __restrict__ Wq, const float4* __restrict__ Sq,
        int m, int k, const float2* f, char* aH, char* aL, int kofs) {
    float v0, v1;
    if (k < CT) {
        float4 w = Wq[m];
        v0 = w.x * f[0].x + w.y * f[1].x + w.z * f[2].x + w.w * f[3].x;
        v1 = w.x * f[0].y + w.y * f[1].y + w.z * f[2].y + w.w * f[3].y;
    } else if (k == 484) { float4 s = Sq[m]; v0 = s.x; v1 = s.y; }
    else if (k == 486)   { float4 s = Sq[m]; v0 = s.z; v1 = s.w; }
    else { v0 = 0.0f; v1 = 0.0f; }
    uint32_t hw, lw;
    asm("cvt.rn.bf16x2.f32 %0, %1, %2;" : "=r"(hw) : "f"(v1), "f"(v0));   // lo=v0, hi=v1
    float l0 = v0 - __uint_as_float(hw << 16);
    float l1 = v1 - __uint_as_float(hw & 0xffff0000u);
    asm("cvt.rn.bf16x2.f32 %0, %1, %2;" : "=r"(lw) : "f"(l1), "f"(l0));
    *(uint32_t*)(aH + m * 80 + kofs) = hw;
    *(uint32_t*)(aL + m * 80 + kofs) = lw;
}

__device__ __forceinline__ void b1fill(int c, char* dstH, int tid) {
    int r = tid >> 1, seg = (tid & 1) * 2;
    const char* sh = (const char*)g_W1h + r * 1024 + c * 64 + seg * 16;
    const char* sl = (const char*)g_W1l + r * 1024 + c * 64 + seg * 16;
    char* dh = dstH + r * 80 + seg * 16;
    char* dl = dstH + TILE1 + r * 80 + seg * 16;
    cp16(dh, sh); cp16(dh + 16, sh + 16);
    cp16(dl, sl); cp16(dl + 16, sl + 16);
}
__device__ __forceinline__ void b2fill(int c, char* dstH, int tid) {
    int r = tid >> 1, seg = (tid & 1) * 2;
    const char* sh = (const char*)g_W2h + r * 256 + c * 64 + seg * 16;
    const char* sl = (const char*)g_W2l + r * 256 + c * 64 + seg * 16;
    char* dh = dstH + r * 80 + seg * 16;
    char* dl = dstH + TILE1 + r * 80 + seg * 16;
    cp16(dh, sh); cp16(dh + 16, sh + 16);
    cp16(dl, sl); cp16(dl + 16, sl + 16);
}

// ---------------- prep kernels ----------------
#define PB_Z   782
#define PB_W1  (PB_Z + 128)
#define PB_W2  (PB_W1 + 64)
#define PB_T   (PB_W2 + 8192)

__global__ void k_prep(const int* __restrict__ e,
                       const float* __restrict__ W1, const float* __restrict__ W2,
                       const float* __restrict__ bb, const float* __restrict__ seg) {
    int bx = blockIdx.x, tid = threadIdx.x;
    if (bx < PB_Z) {
        int i = bx * 256 + tid;
        if (i < NN) g_deg[i] = 0;
        if (bx == 0 && tid < 32) {
            int nz = (e[2 * tid + 1] != 0) ? 1 : 0;
            unsigned m = __ballot_sync(0xffffffffu, nz);
            if (tid == 0) { g_e64 = (m == 0u) ? 1 : 0; g_maxdeg = 0; }
        }
    } else if (bx < PB_W1) {
        int n = bx - PB_Z;
        #pragma unroll
        for (int it = 0; it < 2; it++) {
            int r = it * 256 + tid;
            int col;
            if      (r < CT)   col = r + 2;
            else if (r == 484) col = 0;
            else if (r == 485) col = 1;
            else if (r == 486) col = 486;
            else if (r == 487) col = 487;
            else               col = -1;
            float v = (col >= 0) ? W1[n * KIN + col] : 0.0f;
            __nv_bfloat16 h = __float2bfloat16(v);
            g_W1h[n * 512 + r] = h;
            g_W1l[n * 512 + r] = __float2bfloat16(v - __bfloat162float(h));
        }
    } else if (bx < PB_W2) {
        int n = (bx - PB_W1) * 2 + (tid >> 7), k = tid & 127;
        float v = W2[n * HID + k];
        __nv_bfloat16 h = __float2bfloat16(v);
        g_W2h[n * 128 + k] = h;
        g_W2l[n * 128 + k] = __float2bfloat16(v - __bfloat162float(h));
    } else {
        __shared__ float t[32][33];
        int i = bx - PB_W2;
        int c0 = (i & 15) * 32, p0 = (i >> 4) * 32;
        int tx = tid & 31, ty = tid >> 5;    // 32 x 8
        #pragma unroll
        for (int q = 0; q < 4; q++) {
            int c = c0 + ty + q * 8;
            float v = 0.0f;
            if (c < CT)
                v = (c < CBB) ? bb[(size_t)c * NPIX + p0 + tx]
                              : seg[(size_t)(c - CBB) * NPIX + p0 + tx];
            t[ty + q * 8][tx] = v;
        }
        __syncthreads();
        #pragma unroll
        for (int q = 0; q < 4; q++) {
            int p = p0 + ty + q * 8;
            int c = c0 + tx;
            if (c < CT) g_ft[(size_t)p * CT + c] = t[tx][ty + q * 8];
        }
    }
}

__global__ void k_degree(const void* __restrict__ eptr) {
    const int total = 2 * NEDGE;
    const bool is64 = (g_e64 != 0);
    const long long* __restrict__ e64 = (const long long*)eptr;
    const int* __restrict__ e32 = (const int*)eptr;
    for (int i = blockIdx.x * blockDim.x + threadIdx.x; i < total; i += gridDim.x * blockDim.x) {
        int idx = is64 ? (int)e64[i] : e32[i];
        atomicAdd(&g_deg[idx], 1);
    }
}

__global__ void k_max() {
    int i = blockIdx.x * blockDim.x + threadIdx.x;
    int v = (i < NN) ? g_deg[i] : 0;
    #pragma unroll
    for (int o = 16; o > 0; o >>= 1) v = max(v, __shfl_down_sync(0xffffffffu, v, o));
    if ((threadIdx.x & 31) == 0) atomicMax(&g_maxdeg, v);
}

// ---------------- main: gather + bf16-split mma.sync (ldmatrix frags) ----------------
__global__ void __launch_bounds__(256, 2) k_main(
    const float* __restrict__ verts,
    const float* __restrict__ b1,
    const float* __restrict__ b2,
    float* __restrict__ out)
{
    extern __shared__ char smem[];
    int4*   Pq = (int4*)(smem + PQ_OFF);
    float4* Wq = (float4*)(smem + WQ_OFF);
    float4* Sq = (float4*)(smem + SQ_OFF);

    const int tid = threadIdx.x;
    const int m0 = blockIdx.x * 128;

    // per-node params
    if (tid < 128) {
        int node = min(m0 + tid, NN - 1);
        float vx = verts[2 * node], vy = verts[2 * node + 1];
        float ix = vx * (127.0f / 512.0f), iy = vy * (127.0f / 512.0f);
        float fx = floorf(ix), fy = floorf(iy);
        float wx = ix - fx, wy = iy - fy;
        int x0 = min(max((int)fx, 0), FDIM - 1);
        int x1 = min(x0 + 1, FDIM - 1);
        int y0 = min(max((int)fy, 0), FDIM - 1);
        int y1 = min(y0 + 1, FDIM - 1);
        Pq[tid] = make_int4((y0 * FDIM + x0) * CT, (y0 * FDIM + x1) * CT,
                            (y1 * FDIM + x0) * CT, (y1 * FDIM + x1) * CT);
        Wq[tid] = make_float4((1.0f - wx) * (1.0f - wy), wx * (1.0f - wy),
                              (1.0f - wx) * wy, wx * wy);
        float dg = (float)g_deg[node] / ((float)g_maxdeg + 1e-6f);
        float dx = fminf(vx, 512.0f - vx), dy = fminf(vy, 512.0f - vy);
        Sq[tid] = make_float4(vx * (1.0f / 512.0f), vy * (1.0f / 512.0f),
                              dg, fminf(dx, dy) * (1.0f / 256.0f));
    }
    __syncthreads();

    const int warp = tid >> 5, lane = tid & 31;
    const int g  = lane >> 2, tc = (lane & 3) * 2;    // mma quad group / k-pair
    const int wM = (warp & 3) * 32, wN = (warp >> 2) * 64;
    const int wp   = warp * 2 + (lane >> 4);          // builder m sub-index
    const int kp2  = (lane & 15) * 2;                 // builder k-pair within chunk
    const int kofs = (lane & 15) * 4;                 // builder store byte offset
    // ldmatrix lane selectors
    const int lrow  = (lane & 7) + ((lane >> 3) & 1) * 8;   // A: matrix row
    const int lcolA = (lane >> 4) * 16;                     // A: k-half byte sel
    const int lbrow = lane & 7;                             // B: n row
    const int lbcol = ((lane >> 3) & 1) * 16;               // B: k-half byte sel
    const int lbsel = (lane >> 4);                          // B: 0=hi tile, 1=lo tile

    float acc[2][8][4];
    #pragma unroll
    for (int a = 0; a < 2; a++)
        #pragma unroll
        for (int b = 0; b < 8; b++)
            #pragma unroll
            for (int c = 0; c < 4; c++) acc[a][b][c] = 0.0f;

    // -------- prologue: B chunk0 via cp.async, A chunk0 built --------
    b1fill(0, smem + B1_OFF(0), tid);
    CP_COMMIT();
    #pragma unroll
    for (int it = 0; it < 8; it++) {
        float2 f[4];
        int m = it * 16 + wp;
        bld_issue(Pq, m, kp2, f);
        bld_store(Wq, Sq, m, kp2, f, smem + A1_OFF(0), smem + A1_OFF(0) + TILE1, kofs);
    }
    CP_WAIT0();
    __syncthreads();

    // ================= GEMM1: 16 chunks of 32 =================
    #pragma unroll 1
    for (int c = 0; c < 16; c++) {
        const int buf = c & 1, nxt = buf ^ 1;
        char* Ah = smem + A1_OFF(buf);
        char* Al = Ah + TILE1;
        char* Bh = smem + B1_OFF(buf);
        char* nAh = smem + A1_OFF(nxt);
        char* nAl = nAh + TILE1;
        const bool more = (c < 15);

        if (more) b1fill(c + 1, smem + B1_OFF(nxt), tid);
        else      b2fill(0, smem + B2_OFF, tid);       // prefetch W2 chunk 0
        CP_COMMIT();

        const int kn = (c + 1) * 32 + kp2;
        #pragma unroll
        for (int k16 = 0; k16 < 2; k16++) {
            uint32_t ah0[4], ah1[4], al0[4], al1[4];
            ldsm4(ah0, sm32(Ah + (wM +      lrow) * 80 + k16 * 32 + lcolA));
            ldsm4(ah1, sm32(Ah + (wM + 16 + lrow) * 80 + k16 * 32 + lcolA));
            ldsm4(al0, sm32(Al + (wM +      lrow) * 80 + k16 * 32 + lcolA));
            ldsm4(al1, sm32(Al + (wM + 16 + lrow) * 80 + k16 * 32 + lcolA));
            #pragma unroll
            for (int half = 0; half < 2; half++) {
                const int it = k16 * 4 + half * 2;
                float2 f0[4], f1[4];
                if (more) {
                    bld_issue(Pq, it * 16 + wp, kn, f0);
                    bld_issue(Pq, (it + 1) * 16 + wp, kn, f1);
                }
                #pragma unroll
                for (int q = 0; q < 4; q++) {
                    const int nb = half * 4 + q;
                    uint32_t b[4];
                    ldsm4(b, sm32(Bh + (wN + nb * 8 + lbrow) * 80 + k16 * 32 + lbcol + lbsel * TILE1));
                    mma16816(acc[0][nb], ah0, b[0], b[1]);
                    mma16816(acc[0][nb], ah0, b[2], b[3]);
                    mma16816(acc[0][nb], al0, b[0], b[1]);
                    mma16816(acc[1][nb], ah1, b[0], b[1]);
                    mma16816(acc[1][nb], ah1, b[2], b[3]);
                    mma16816(acc[1][nb], al1, b[0], b[1]);
                }
                if (more) {
                    bld_store(Wq, Sq, it * 16 + wp, kn, f0, nAh, nAl, kofs);
                    bld_store(Wq, Sq, (it + 1) * 16 + wp, kn, f1, nAh, nAl, kofs);
                }
            }
        }
        CP_WAIT0();
        __syncthreads();
    }

    // -------- epilogue 1: h1 = relu(D1 + b1) -> bf16 hi/lo smem tile --------
    {
        char* A2h = smem + A2H_OFF;
        char* A2l = smem + A2L_OFF;
        #pragma unroll
        for (int mb = 0; mb < 2; mb++) {
            int row = wM + mb * 16 + g;
            #pragma unroll
            for (int nb = 0; nb < 8; nb++) {
                int col = wN + nb * 8 + tc;
                float2 bb = *(const float2*)(b1 + col);
                float v0 = fmaxf(acc[mb][nb][0] + bb.x, 0.0f);
                float v1 = fmaxf(acc[mb][nb][1] + bb.y, 0.0f);
                float v2 = fmaxf(acc[mb][nb][2] + bb.x, 0.0f);
                float v3 = fmaxf(acc[mb][nb][3] + bb.y, 0.0f);
                uint32_t h0, l0w, h1w, l1w;
                asm("cvt.rn.bf16x2.f32 %0, %1, %2;" : "=r"(h0) : "f"(v1), "f"(v0));
                float r0 = v0 - __uint_as_float(h0 << 16);
                float r1 = v1 - __uint_as_float(h0 & 0xffff0000u);
                asm("cvt.rn.bf16x2.f32 %0, %1, %2;" : "=r"(l0w) : "f"(r1), "f"(r0));
                asm("cvt.rn.bf16x2.f32 %0, %1, %2;" : "=r"(h1w) : "f"(v3), "f"(v2));
                float r2 = v2 - __uint_as_float(h1w << 16);
                float r3 = v3 - __uint_as_float(h1w & 0xffff0000u);
                asm("cvt.rn.bf16x2.f32 %0, %1, %2;" : "=r"(l1w) : "f"(r3), "f"(r2));
                *(uint32_t*)(A2h + row * A2_STR + col * 2) = h0;
                *(uint32_t*)(A2l + row * A2_STR + col * 2) = l0w;
                *(uint32_t*)(A2h + (row + 8) * A2_STR + col * 2) = h1w;
                *(uint32_t*)(A2l + (row + 8) * A2_STR + col * 2) = l1w;
            }
        }
    }
    #pragma unroll
    for (int a = 0; a < 2; a++)
        #pragma unroll
        for (int b = 0; b < 8; b++)
            #pragma unroll
            for (int c = 0; c < 4; c++) acc[a][b][c] = 0.0f;
    __syncthreads();

    // ================= GEMM2: 4 chunks of 32 (single B2 buffer) =================
    #pragma unroll 1
    for (int c2 = 0; c2 < 4; c2++) {
        if (c2 > 0) {
            __syncthreads();
            b2fill(c2, smem + B2_OFF, tid);
            CP_COMMIT(); CP_WAIT0();
            __syncthreads();
        }
        char* A2h = smem + A2H_OFF + c2 * 64;
        char* A2l = smem + A2L_OFF + c2 * 64;
        char* Bh = smem + B2_OFF;
        #pragma unroll
        for (int k16 = 0; k16 < 2; k16++) {
            uint32_t ah0[4], ah1[4], al0[4], al1[4];
            ldsm4(ah0, sm32(A2h + (wM +      lrow) * A2_STR + k16 * 32 + lcolA));
            ldsm4(ah1, sm32(A2h + (wM + 16 + lrow) * A2_STR + k16 * 32 + lcolA));
            ldsm4(al0, sm32(A2l + (wM +      lrow) * A2_STR + k16 * 32 + lcolA));
            ldsm4(al1, sm32(A2l + (wM + 16 + lrow) * A2_STR + k16 * 32 + lcolA));
            #pragma unroll
            for (int nb = 0; nb < 8; nb++) {
                uint32_t b[4];
                ldsm4(b, sm32(Bh + (wN + nb * 8 + lbrow) * 80 + k16 * 32 + lbcol + lbsel * TILE1));
                mma16816(acc[0][nb], ah0, b[0], b[1]);
                mma16816(acc[0][nb], ah0, b[2], b[3]);
                mma16816(acc[0][nb], al0, b[0], b[1]);
                mma16816(acc[1][nb], ah1, b[0], b[1]);
                mma16816(acc[1][nb], ah1, b[2], b[3]);
                mma16816(acc[1][nb], al1, b[0], b[1]);
            }
        }
    }

    // -------- epilogue 2: out = relu(D2 + b2) --------
    #pragma unroll
    for (int mb = 0; mb < 2; mb++) {
        int m1 = m0 + wM + mb * 16 + g;
        int m2 = m1 + 8;
        #pragma unroll
        for (int nb = 0; nb < 8; nb++) {
            int col = wN + nb * 8 + tc;
            float2 bb = *(const float2*)(b2 + col);
            if (m1 < NN) {
                float2 v = make_float2(fmaxf(acc[mb][nb][0] + bb.x, 0.0f),
                                       fmaxf(acc[mb][nb][1] + bb.y, 0.0f));
                *(float2*)(out + (size_t)m1 * HID + col) = v;
            }
            if (m2 < NN) {
                float2 v = make_float2(fmaxf(acc[mb][nb][2] + bb.x, 0.0f),
                                       fmaxf(acc[mb][nb][3] + bb.y, 0.0f));
                *(float2*)(out + (size_t)m2 * HID + col) = v;
            }
        }
    }
}

// ---------------- launch ----------------
extern "C" void kernel_launch(void* const* d_in, const int* in_sizes, int n_in,
                              void* d_out, int out_size)
{
    const float* verts = (const float*)d_in[0];
    const float* bb    = (const float*)d_in[1];
    const float* seg   = (const float*)d_in[2];
    const void*  edges = d_in[3];
    const float* W1    = (const float*)d_in[4];
    const float* b1    = (const float*)d_in[5];
    const float* W2    = (const float*)d_in[6];
    const float* b2    = (const float*)d_in[7];
    float* out = (float*)d_out;

    k_prep<<<PB_T, 256>>>((const int*)edges, W1, W2, bb, seg);
    k_degree<<<2048, 256>>>(edges);
    k_max<<<(NN + 255) / 256, 256>>>();

    cudaFuncSetAttribute(k_main, cudaFuncAttributeMaxDynamicSharedMemorySize, SMEM_BYTES);
    k_main<<<(NN + 127) / 128, 256, SMEM_BYTES>>>(verts, b1, b2, out);
}